// round 2
// baseline (speedup 1.0000x reference)
#include <cuda_runtime.h>

#define XD 128
#define YD 128
#define ZD 8
#define ED 64
#define KD 3
#define NITER 3
#define FHD 96
#define FWD 320
#define NPTS (XD*YD*ZD)
#define HW (FHD*FWD)
#define NTHR 256
#define BPAD 66

// device scratch (no allocation allowed)
__device__ float g_imgT[HW * ED];   // (H,W,C) image, 7.9 MB

typedef unsigned long long ull;

__device__ __forceinline__ ull pk2(float x, float y) {
    ull r; asm("mov.b64 %0,{%1,%2};" : "=l"(r) : "f"(x), "f"(y)); return r;
}
__device__ __forceinline__ ull splat(float x) { return pk2(x, x); }
__device__ __forceinline__ void unpk(ull v, float& x, float& y) {
    asm("mov.b64 {%0,%1},%2;" : "=f"(x), "=f"(y) : "l"(v));
}
__device__ __forceinline__ ull fma2(ull a, ull b, ull c) {
    ull d; asm("fma.rn.f32x2 %0,%1,%2,%3;" : "=l"(d) : "l"(a), "l"(b), "l"(c)); return d;
}
__device__ __forceinline__ ull add2(ull a, ull b) {
    ull d; asm("add.rn.f32x2 %0,%1,%2;" : "=l"(d) : "l"(a), "l"(b)); return d;
}

// ---------------------------------------------------------------------------
// Kernel 1: coalesced transpose img (C,H,W) -> (H,W,C) via shared tile
// ---------------------------------------------------------------------------
__global__ __launch_bounds__(256) void transpose_img_kernel(const float* __restrict__ img) {
    __shared__ float tile[32][65];
    const int r0 = blockIdx.x * 32;
    const int t  = threadIdx.x;
    const int tx = t & 31, ty = t >> 5;
    #pragma unroll
    for (int k = 0; k < 8; ++k) {
        int c = k * 8 + ty;
        tile[tx][c] = img[c * HW + r0 + tx];
    }
    __syncthreads();
    #pragma unroll
    for (int k = 0; k < 8; ++k) {
        int row = k * 4 + (t >> 6);
        int c   = t & 63;
        g_imgT[(r0 + row) * ED + c] = tile[row][c];
    }
}

// ---------------------------------------------------------------------------
// Kernel 2: fused pipeline. CTA = 128 points (16 xy-cells x 8 z), 256 threads.
// Dynamic smem layout (floats):
//   Bs  [128][66]   8448
//   Wl  [64][64]    4096
//   Wd  [64][10]     640   (packed W_off|W_w)
//   Ls  [128][12]   1536   (logits)
//   Cx  [128], Cy [128]
// total 14976 floats = 59904 bytes
// ---------------------------------------------------------------------------
__global__ __launch_bounds__(NTHR) void bev_kernel(
    const float* __restrict__ Tv,     const float* __restrict__ intr,
    const float* __restrict__ bev_in,
    const float* __restrict__ W_off,  const float* __restrict__ b_off,
    const float* __restrict__ s_off,
    const float* __restrict__ W_w,    const float* __restrict__ b_w,
    const float* __restrict__ W_l,    const float* __restrict__ b_l,
    const float* __restrict__ ln_g,   const float* __restrict__ ln_b,
    float* __restrict__ out)
{
    extern __shared__ float sm[];
    float* Bs = sm;                  // [128][66]
    float* Wl = sm + 8448;           // [64][64]
    float* Wd = sm + 8448 + 4096;    // [64][10]
    float* Ls = Wd + 640;            // [128][12]
    float* Cx = Ls + 1536;
    float* Cy = Cx + 128;

    const int t   = threadIdx.x;
    const int blk = blockIdx.x;
    const int p0  = blk * 128;

    // ---- init B state ----
    for (int u = t; u < 128 * ED / 2; u += NTHR) {
        float2 v = ((const float2*)bev_in)[(size_t)p0 * 32 + u];
        int row = u >> 5, col = (u & 31) << 1;
        *(float2*)&Bs[row * BPAD + col] = v;
    }
    // ---- per-point projected coords (iteration-invariant) ----
    if (t < 128) {
        int p  = p0 + t;
        int iz = p & (ZD - 1);
        int ixy = p >> 3;
        int iy = ixy & (YD - 1);
        int ix = ixy >> 7;
        float gx = (float)ix * 0.8f;
        float gy = 51.2f - (float)iy * 0.8f;
        float gz = (float)iz * 0.5f - 2.5f;
        float q0 = Tv[0]*gx + Tv[1]*gy + Tv[2]*gz  + Tv[3];
        float q1 = Tv[4]*gx + Tv[5]*gy + Tv[6]*gz  + Tv[7];
        float q2 = Tv[8]*gx + Tv[9]*gy + Tv[10]*gz + Tv[11];
        float r0 = intr[0]*q0 + intr[1]*q1 + intr[2]*q2;
        float r1 = intr[3]*q0 + intr[4]*q1 + intr[5]*q2;
        float r2 = intr[6]*q0 + intr[7]*q1 + intr[8]*q2;
        float invz = 1.0f / r2;
        Cx[t] = r0 * invz * (1.0f / 640.0f) - 1.0f;
        Cy[t] = r1 * invz * (1.0f / 192.0f) - 1.0f;
    }
    // ---- stage Wd for iter 0 ----
    for (int u = t; u < 640; u += NTHR) {
        int e = u / 10, j = u - e * 10;
        float v = 0.0f;
        if (j < 6)      v = W_off[e * 6 + j];
        else if (j < 9) v = W_w[e * 3 + (j - 6)];
        Wd[u] = v;
    }
    __syncthreads();

    const int gi = t >> 3;   // 0..31 : point group (4 pts)
    const int gj = t & 7;    // 0..7  : channel group (8 ch)

    for (int i = 0; i < NITER; ++i) {
        // ===== dots: 1 thread per point, 10 logits via f32x2 =====
        if (t < 128) {
            ull acc[5] = {0, 0, 0, 0, 0};
            const float* brow = &Bs[t * BPAD];
            #pragma unroll 4
            for (int e = 0; e < ED; ++e) {
                ull bs = splat(brow[e]);
                const ull* wrow = (const ull*)&Wd[e * 10];
                #pragma unroll
                for (int q = 0; q < 5; ++q) acc[q] = fma2(bs, wrow[q], acc[q]);
            }
            #pragma unroll
            for (int q = 0; q < 5; ++q) {
                float x, y; unpk(acc[q], x, y);
                Ls[t * 12 + 2 * q] = x; Ls[t * 12 + 2 * q + 1] = y;
            }
        }
        __syncthreads();

        // ===== sample: 2 threads per point, 32 channels each =====
        {
            const int pt = t >> 1, hf = t & 1;
            float lg[9];
            #pragma unroll
            for (int j = 0; j < 9; ++j) lg[j] = Ls[pt * 12 + j];
            const float sc = s_off[i];
            float off[6];
            #pragma unroll
            for (int j = 0; j < 6; ++j) off[j] = (lg[j] + b_off[i * 6 + j]) * sc;
            float l0 = lg[6] + b_w[i * 3 + 0];
            float l1 = lg[7] + b_w[i * 3 + 1];
            float l2 = lg[8] + b_w[i * 3 + 2];
            float mx = fmaxf(l0, fmaxf(l1, l2));
            float e0 = __expf(l0 - mx), e1 = __expf(l1 - mx), e2 = __expf(l2 - mx);
            float inv = 1.0f / (e0 + e1 + e2);
            float wk[3] = {e0 * inv, e1 * inv, e2 * inv};
            float cx = Cx[pt], cy = Cy[pt];

            ull acc[16];
            #pragma unroll
            for (int q = 0; q < 16; ++q) acc[q] = 0ull;

            #pragma unroll
            for (int k = 0; k < KD; ++k) {
                float px = ((cx + off[2 * k]     + 1.0f) * (float)FWD - 1.0f) * 0.5f;
                float py = ((cy + off[2 * k + 1] + 1.0f) * (float)FHD - 1.0f) * 0.5f;
                float fx0 = floorf(px), fy0 = floorf(py);
                int x0 = (int)fx0, y0 = (int)fy0;
                float wx1 = px - fx0, wy1 = py - fy0;
                float cw0 = (1.0f - wx1) * (1.0f - wy1);
                float cw1 = wx1 * (1.0f - wy1);
                float cw2 = (1.0f - wx1) * wy1;
                float cw3 = wx1 * wy1;
                float cw[4] = {cw0, cw1, cw2, cw3};
                #pragma unroll
                for (int c = 0; c < 4; ++c) {
                    int xi = x0 + (c & 1), yi = y0 + (c >> 1);
                    if ((unsigned)xi < (unsigned)FWD && (unsigned)yi < (unsigned)FHD) {
                        ull ws = splat(wk[k] * cw[c]);
                        const ull* rp = (const ull*)(g_imgT + (((size_t)yi * FWD + xi) << 6) + (hf << 5));
                        #pragma unroll
                        for (int q = 0; q < 16; ++q)
                            acc[q] = fma2(ws, rp[q], acc[q]);
                    }
                }
            }
            float* brow = &Bs[pt * BPAD + (hf << 5)];
            #pragma unroll
            for (int q = 0; q < 16; ++q) {
                ull old = *(ull*)&brow[2 * q];
                *(ull*)&brow[2 * q] = add2(old, acc[q]);
            }
        }
        // stage W_l for this iteration (safe: last read was before prev sync)
        {
            const float4* src = (const float4*)(W_l + i * 4096);
            #pragma unroll
            for (int u = 0; u < 4; ++u)
                ((float4*)Wl)[t + u * NTHR] = src[t + u * NTHR];
        }
        __syncthreads();

        // ===== matvec GEMM: thread tile 4 pts x 8 ch =====
        ull h[4][4];
        {
            const ull* blp = (const ull*)(b_l + i * ED + 8 * gj);
            ull bl0 = blp[0], bl1 = blp[1], bl2 = blp[2], bl3 = blp[3];
            #pragma unroll
            for (int p = 0; p < 4; ++p) { h[p][0] = bl0; h[p][1] = bl1; h[p][2] = bl2; h[p][3] = bl3; }
        }
        #pragma unroll 2
        for (int e = 0; e < ED; ++e) {
            const ull* wrow = (const ull*)&Wl[e * ED + 8 * gj];
            ull w0 = wrow[0], w1 = wrow[1], w2 = wrow[2], w3 = wrow[3];
            #pragma unroll
            for (int p = 0; p < 4; ++p) {
                ull bs = splat(Bs[(4 * gi + p) * BPAD + e]);
                h[p][0] = fma2(bs, w0, h[p][0]);
                h[p][1] = fma2(bs, w1, h[p][1]);
                h[p][2] = fma2(bs, w2, h[p][2]);
                h[p][3] = fma2(bs, w3, h[p][3]);
            }
        }
        __syncthreads();   // all B reads done before LN writes B

        // ===== LayerNorm + residual =====
        {
            float s1[4], s2[4];
            #pragma unroll
            for (int p = 0; p < 4; ++p) {
                s1[p] = 0.0f; s2[p] = 0.0f;
                #pragma unroll
                for (int q = 0; q < 4; ++q) {
                    float a, b; unpk(h[p][q], a, b);
                    s1[p] += a + b;
                    s2[p] += a * a + b * b;
                }
            }
            #pragma unroll
            for (int o = 1; o < 8; o <<= 1) {
                #pragma unroll
                for (int p = 0; p < 4; ++p) {
                    s1[p] += __shfl_xor_sync(0xffffffffu, s1[p], o);
                    s2[p] += __shfl_xor_sync(0xffffffffu, s2[p], o);
                }
            }
            float gg[8], lb[8];
            {
                const float2* gp = (const float2*)(ln_g + i * ED + 8 * gj);
                const float2* bp = (const float2*)(ln_b + i * ED + 8 * gj);
                #pragma unroll
                for (int q = 0; q < 4; ++q) {
                    float2 g2 = gp[q], b2 = bp[q];
                    gg[2*q] = g2.x; gg[2*q+1] = g2.y;
                    lb[2*q] = b2.x; lb[2*q+1] = b2.y;
                }
            }
            #pragma unroll
            for (int p = 0; p < 4; ++p) {
                float mu  = s1[p] * (1.0f / ED);
                float var = s2[p] * (1.0f / ED) - mu * mu;
                float rstd = rsqrtf(var + 1e-5f);
                float* brw = &Bs[(4 * gi + p) * BPAD + 8 * gj];
                #pragma unroll
                for (int q = 0; q < 4; ++q) {
                    float a, b; unpk(h[p][q], a, b);
                    float hn0 = (a - mu) * rstd * gg[2*q] + lb[2*q];
                    float hn1 = (b - mu) * rstd * gg[2*q+1] + lb[2*q+1];
                    float ox, oy; unpk(*(ull*)&brw[2 * q], ox, oy);
                    *(ull*)&brw[2 * q] = pk2(ox + hn0, oy + hn1);
                }
            }
        }
        // stage Wd for next iteration
        if (i < NITER - 1) {
            const float* Wo = W_off + (i + 1) * (ED * 6);
            const float* Ww = W_w   + (i + 1) * (ED * 3);
            for (int u = t; u < 640; u += NTHR) {
                int e = u / 10, j = u - e * 10;
                float v = 0.0f;
                if (j < 6)      v = Wo[e * 6 + j];
                else if (j < 9) v = Ww[e * 3 + (j - 6)];
                Wd[u] = v;
            }
        }
        __syncthreads();
    }

    // ===== fused Z-mean output: CTA covers 16 (x,y) cells =====
    #pragma unroll
    for (int pass = 0; pass < 4; ++pass) {
        int cell = (t >> 6) + pass * 4;
        int e = t & 63;
        float a = 0.0f;
        #pragma unroll
        for (int z = 0; z < ZD; ++z)
            a += Bs[(cell * 8 + z) * BPAD + e];
        int gc = blk * 16 + cell;
        int ixx = gc >> 7;
        int iyy = gc & 127;
        out[e * (XD * YD) + iyy * XD + ixx] = a * 0.125f;
    }
}

// ---------------------------------------------------------------------------
extern "C" void kernel_launch(void* const* d_in, const int* in_sizes, int n_in,
                              void* d_out, int out_size) {
    const float* Tv     = (const float*)d_in[0];
    const float* intr   = (const float*)d_in[1];
    const float* img    = (const float*)d_in[2];
    const float* bev_in = (const float*)d_in[3];
    const float* W_off  = (const float*)d_in[4];
    const float* b_off  = (const float*)d_in[5];
    const float* s_off  = (const float*)d_in[6];
    const float* W_w    = (const float*)d_in[7];
    const float* b_w    = (const float*)d_in[8];
    const float* W_l    = (const float*)d_in[9];
    const float* b_l    = (const float*)d_in[10];
    const float* ln_g   = (const float*)d_in[11];
    const float* ln_b   = (const float*)d_in[12];
    float* out = (float*)d_out;

    const int SMEM = 14976 * 4;
    cudaFuncSetAttribute(bev_kernel, cudaFuncAttributeMaxDynamicSharedMemorySize, SMEM);

    transpose_img_kernel<<<HW / 32, 256>>>(img);
    bev_kernel<<<NPTS / 128, NTHR, SMEM>>>(Tv, intr, bev_in,
                                           W_off, b_off, s_off,
                                           W_w, b_w, W_l, b_l, ln_g, ln_b, out);
}

// round 3
// speedup vs baseline: 2.6659x; 2.6659x over previous
#include <cuda_runtime.h>

#define XD 128
#define YD 128
#define ZD 8
#define ED 64
#define NITER 3
#define FHD 96
#define FWD 320
#define NPTS (XD*YD*ZD)
#define HW (FHD*FWD)

typedef unsigned long long ull;

__device__ float g_imgT[HW * ED];      // (H,W,C) image, 7.9 MB
__device__ float g_Wd[NITER * ED * 12]; // packed [iter][e][12]: Woff(6)|Ww(3)|pad

__device__ __forceinline__ ull pk2(float x, float y) {
    ull r; asm("mov.b64 %0,{%1,%2};" : "=l"(r) : "f"(x), "f"(y)); return r;
}
__device__ __forceinline__ ull splat(float x) { return pk2(x, x); }
__device__ __forceinline__ void unpk(ull v, float& x, float& y) {
    asm("mov.b64 {%0,%1},%2;" : "=f"(x), "=f"(y) : "l"(v));
}
__device__ __forceinline__ ull fma2(ull a, ull b, ull c) {
    ull d; asm("fma.rn.f32x2 %0,%1,%2,%3;" : "=l"(d) : "l"(a), "l"(b), "l"(c)); return d;
}
__device__ __forceinline__ ull add2(ull a, ull b) {
    ull d; asm("add.rn.f32x2 %0,%1,%2;" : "=l"(d) : "l"(a), "l"(b)); return d;
}

// ---------------------------------------------------------------------------
// Kernel 1: coalesced transpose img (C,H,W) -> (H,W,C)
// ---------------------------------------------------------------------------
__global__ __launch_bounds__(256) void transpose_img_kernel(const float* __restrict__ img) {
    __shared__ float tile[32][65];
    const int r0 = blockIdx.x * 32;
    const int t  = threadIdx.x;
    const int tx = t & 31, ty = t >> 5;
    #pragma unroll
    for (int k = 0; k < 8; ++k) {
        int c = k * 8 + ty;
        tile[tx][c] = img[c * HW + r0 + tx];
    }
    __syncthreads();
    #pragma unroll
    for (int k = 0; k < 8; ++k) {
        int row = k * 4 + (t >> 6);
        int c   = t & 63;
        g_imgT[(r0 + row) * ED + c] = tile[row][c];
    }
}

// ---------------------------------------------------------------------------
// Kernel 1b: pack W_off | W_w into g_Wd [iter][64][12]
// ---------------------------------------------------------------------------
__global__ void pack_wd_kernel(const float* __restrict__ W_off, const float* __restrict__ W_w) {
    int idx = blockIdx.x * blockDim.x + threadIdx.x;
    if (idx >= NITER * ED * 12) return;
    int i = idx / (ED * 12);
    int r = idx - i * (ED * 12);
    int e = r / 12, j = r - e * 12;
    float v = 0.0f;
    if (j < 6)      v = W_off[i * ED * 6 + e * 6 + j];
    else if (j < 9) v = W_w[i * ED * 3 + e * 3 + (j - 6)];
    g_Wd[idx] = v;
}

// ---------------------------------------------------------------------------
// Kernel 2: fused pipeline. 256 threads = 8 warps; each LANE owns one point.
// smem (floats): Wl[4096] | Wd[768] | Gs[8][32*28]=7168 | buf[8][1088]=8704
// total 20736 floats = 82944 bytes
// ---------------------------------------------------------------------------
__global__ __launch_bounds__(256, 2) void bev_kernel(
    const float* __restrict__ Tv,     const float* __restrict__ intr,
    const float* __restrict__ bev_in,
    const float* __restrict__ b_off,  const float* __restrict__ s_off,
    const float* __restrict__ b_w,
    const float* __restrict__ W_l,    const float* __restrict__ b_l,
    const float* __restrict__ ln_g,   const float* __restrict__ ln_b,
    float* __restrict__ out)
{
    extern __shared__ float sm[];
    float* sWl = sm;                       // [64][64]
    float* sWd = sm + 4096;                // [64][12]
    const int t    = threadIdx.x;
    const int warp = t >> 5;
    const int lane = t & 31;
    float* Gsw  = sm + 4096 + 768 + warp * (32 * 28);   // [32][28]
    float* bufw = sm + 4096 + 768 + 7168 + warp * 1088; // Fs[16][66] / Hs[32][34]

    const int p = blockIdx.x * 256 + t;    // this lane's point

    // ---- projected base coords for own point ----
    float pxb, pyb;
    {
        int iz = p & 7;
        int ixy = p >> 3;
        int iy = ixy & 127;
        int ix = ixy >> 7;
        float gx = (float)ix * 0.8f;
        float gy = 51.2f - (float)iy * 0.8f;
        float gz = (float)iz * 0.5f - 2.5f;
        float q0 = Tv[0]*gx + Tv[1]*gy + Tv[2]*gz  + Tv[3];
        float q1 = Tv[4]*gx + Tv[5]*gy + Tv[6]*gz  + Tv[7];
        float q2 = Tv[8]*gx + Tv[9]*gy + Tv[10]*gz + Tv[11];
        float r0 = intr[0]*q0 + intr[1]*q1 + intr[2]*q2;
        float r1 = intr[3]*q0 + intr[4]*q1 + intr[5]*q2;
        float r2 = intr[6]*q0 + intr[7]*q1 + intr[8]*q2;
        float invz = 1.0f / r2;
        float cx = r0 * invz * (1.0f / 640.0f) - 1.0f;
        float cy = r1 * invz * (1.0f / 192.0f) - 1.0f;
        pxb = cx * 160.0f + 159.5f;
        pyb = cy * 48.0f  + 47.5f;
    }

    // ---- load B state into registers via smem transpose ----
    ull bb[32];
    const int pwarp0 = blockIdx.x * 256 + warp * 32;  // warp's first point
    #pragma unroll
    for (int g = 0; g < 2; ++g) {
        #pragma unroll
        for (int q = 0; q < 16; ++q) {
            int pt = pwarp0 + g * 16 + q;
            ull v = *((const ull*)(bev_in + (size_t)pt * ED) + lane);
            *(ull*)&bufw[q * 66 + 2 * lane] = v;
        }
        __syncwarp();
        if ((lane >> 4) == g) {
            #pragma unroll
            for (int q = 0; q < 32; ++q)
                bb[q] = *(ull*)&bufw[(lane & 15) * 66 + 2 * q];
        }
        __syncwarp();
    }

    for (int i = 0; i < NITER; ++i) {
        // ---- stage weights (CTA-wide) ----
        __syncthreads();
        {
            const float4* src = (const float4*)(W_l + i * 4096);
            #pragma unroll
            for (int u = 0; u < 4; ++u)
                ((float4*)sWl)[t + u * 256] = src[t + u * 256];
            if (t < 192)
                ((float4*)sWd)[t] = ((const float4*)(g_Wd + i * 768))[t];
        }
        __syncthreads();

        // ===== dots: own point, 10 logits, weight rows broadcast =====
        float d[10];
        {
            ull acc[5] = {0, 0, 0, 0, 0};
            #pragma unroll
            for (int ep = 0; ep < 32; ++ep) {
                float be0, be1; unpk(bb[ep], be0, be1);
                ull bs0 = splat(be0), bs1 = splat(be1);
                const ulonglong2* w0 = (const ulonglong2*)&sWd[(2 * ep) * 12];
                const ulonglong2* w1 = (const ulonglong2*)&sWd[(2 * ep + 1) * 12];
                ulonglong2 wa = w0[0], wb = w0[1], wc = w0[2];
                acc[0] = fma2(bs0, wa.x, acc[0]); acc[1] = fma2(bs0, wa.y, acc[1]);
                acc[2] = fma2(bs0, wb.x, acc[2]); acc[3] = fma2(bs0, wb.y, acc[3]);
                acc[4] = fma2(bs0, wc.x, acc[4]);
                wa = w1[0]; wb = w1[1]; wc = w1[2];
                acc[0] = fma2(bs1, wa.x, acc[0]); acc[1] = fma2(bs1, wa.y, acc[1]);
                acc[2] = fma2(bs1, wb.x, acc[2]); acc[3] = fma2(bs1, wb.y, acc[3]);
                acc[4] = fma2(bs1, wc.x, acc[4]);
            }
            #pragma unroll
            for (int q = 0; q < 5; ++q) unpk(acc[q], d[2 * q], d[2 * q + 1]);
        }

        // ===== G1: per-lane offsets/softmax -> per-point gather table =====
        {
            const float sc = __ldg(s_off + i);
            float off[6];
            #pragma unroll
            for (int j = 0; j < 6; ++j) off[j] = (d[j] + __ldg(b_off + i * 6 + j)) * sc;
            float l0 = d[6] + __ldg(b_w + i * 3 + 0);
            float l1 = d[7] + __ldg(b_w + i * 3 + 1);
            float l2 = d[8] + __ldg(b_w + i * 3 + 2);
            float mx = fmaxf(l0, fmaxf(l1, l2));
            float e0 = __expf(l0 - mx), e1 = __expf(l1 - mx), e2 = __expf(l2 - mx);
            float inv = 1.0f / (e0 + e1 + e2);
            float wk[3] = {e0 * inv, e1 * inv, e2 * inv};
            float* grow = Gsw + lane * 28;
            #pragma unroll
            for (int k = 0; k < 3; ++k) {
                float px = fmaf(off[2 * k],     160.0f, pxb);
                float py = fmaf(off[2 * k + 1],  48.0f, pyb);
                float fx = floorf(px), fy = floorf(py);
                int x0 = (int)fx, y0 = (int)fy;
                float wx1 = px - fx, wy1 = py - fy;
                float wx0 = 1.0f - wx1, wy0 = 1.0f - wy1;
                bool vx0 = (unsigned)x0 < (unsigned)FWD, vx1 = (unsigned)(x0 + 1) < (unsigned)FWD;
                bool vy0 = (unsigned)y0 < (unsigned)FHD, vy1 = (unsigned)(y0 + 1) < (unsigned)FHD;
                int xc0 = min(max(x0, 0), FWD - 1), xc1 = min(max(x0 + 1, 0), FWD - 1);
                int yc0 = min(max(y0, 0), FHD - 1), yc1 = min(max(y0 + 1, 0), FHD - 1);
                int rA = yc0 * FWD, rB = yc1 * FWD;
                float W = wk[k];
                float w00 = (vx0 && vy0) ? W * wx0 * wy0 : 0.0f;
                float w01 = (vx1 && vy0) ? W * wx1 * wy0 : 0.0f;
                float w10 = (vx0 && vy1) ? W * wx0 * wy1 : 0.0f;
                float w11 = (vx1 && vy1) ? W * wx1 * wy1 : 0.0f;
                *(float4*)(grow + k * 8) = make_float4(
                    __int_as_float((rA + xc0) << 6), __int_as_float((rA + xc1) << 6),
                    __int_as_float((rB + xc0) << 6), __int_as_float((rB + xc1) << 6));
                *(float4*)(grow + k * 8 + 4) = make_float4(w00, w01, w10, w11);
            }
        }
        __syncwarp();

        // ===== G2: warp-per-point gather (channel-parallel), fold into bb =====
        #pragma unroll 1
        for (int g = 0; g < 2; ++g) {
            #pragma unroll 1
            for (int q = 0; q < 16; ++q) {
                const float* grow = Gsw + (g * 16 + q) * 28;
                float a0 = 0.0f, a1 = 0.0f;
                #pragma unroll
                for (int k = 0; k < 3; ++k) {
                    float4 A  = *(const float4*)(grow + k * 8);
                    float4 Wt = *(const float4*)(grow + k * 8 + 4);
                    float2 v;
                    v = *(const float2*)(g_imgT + __float_as_int(A.x) + 2 * lane);
                    a0 = fmaf(Wt.x, v.x, a0); a1 = fmaf(Wt.x, v.y, a1);
                    v = *(const float2*)(g_imgT + __float_as_int(A.y) + 2 * lane);
                    a0 = fmaf(Wt.y, v.x, a0); a1 = fmaf(Wt.y, v.y, a1);
                    v = *(const float2*)(g_imgT + __float_as_int(A.z) + 2 * lane);
                    a0 = fmaf(Wt.z, v.x, a0); a1 = fmaf(Wt.z, v.y, a1);
                    v = *(const float2*)(g_imgT + __float_as_int(A.w) + 2 * lane);
                    a0 = fmaf(Wt.w, v.x, a0); a1 = fmaf(Wt.w, v.y, a1);
                }
                *(ull*)&bufw[q * 66 + 2 * lane] = pk2(a0, a1);
            }
            __syncwarp();
            if ((lane >> 4) == g) {
                #pragma unroll
                for (int q = 0; q < 32; ++q)
                    bb[q] = add2(bb[q], *(ull*)&bufw[(lane & 15) * 66 + 2 * q]);
            }
            __syncwarp();
        }

        // ===== matvec 64x64 (two 32-output halves) + LayerNorm residual =====
        float s1 = 0.0f, s2 = 0.0f;
        ull h[16];

        // half 0: outputs 0..31 -> stash to Hs
        {
            #pragma unroll
            for (int q = 0; q < 8; ++q) {
                ulonglong2 bl = __ldg((const ulonglong2*)(b_l + i * ED) + q);
                h[2 * q] = bl.x; h[2 * q + 1] = bl.y;
            }
            #pragma unroll
            for (int ep = 0; ep < 32; ++ep) {
                float be0, be1; unpk(bb[ep], be0, be1);
                ull bs0 = splat(be0), bs1 = splat(be1);
                const float* w0 = &sWl[(2 * ep) * ED];
                const float* w1 = w0 + ED;
                #pragma unroll
                for (int q = 0; q < 8; ++q) {
                    ulonglong2 a = *(const ulonglong2*)(w0 + 4 * q);
                    h[2 * q]     = fma2(bs0, a.x, h[2 * q]);
                    h[2 * q + 1] = fma2(bs0, a.y, h[2 * q + 1]);
                    ulonglong2 b = *(const ulonglong2*)(w1 + 4 * q);
                    h[2 * q]     = fma2(bs1, b.x, h[2 * q]);
                    h[2 * q + 1] = fma2(bs1, b.y, h[2 * q + 1]);
                }
            }
            #pragma unroll
            for (int q = 0; q < 16; ++q) {
                float a, b; unpk(h[q], a, b);
                s1 += a + b;
                s2 = fmaf(a, a, s2); s2 = fmaf(b, b, s2);
                *(ull*)&bufw[lane * 34 + 2 * q] = h[q];
            }
        }
        // half 1: outputs 32..63 -> keep in regs
        {
            #pragma unroll
            for (int q = 0; q < 8; ++q) {
                ulonglong2 bl = __ldg((const ulonglong2*)(b_l + i * ED + 32) + q);
                h[2 * q] = bl.x; h[2 * q + 1] = bl.y;
            }
            #pragma unroll
            for (int ep = 0; ep < 32; ++ep) {
                float be0, be1; unpk(bb[ep], be0, be1);
                ull bs0 = splat(be0), bs1 = splat(be1);
                const float* w0 = &sWl[(2 * ep) * ED + 32];
                const float* w1 = w0 + ED;
                #pragma unroll
                for (int q = 0; q < 8; ++q) {
                    ulonglong2 a = *(const ulonglong2*)(w0 + 4 * q);
                    h[2 * q]     = fma2(bs0, a.x, h[2 * q]);
                    h[2 * q + 1] = fma2(bs0, a.y, h[2 * q + 1]);
                    ulonglong2 b = *(const ulonglong2*)(w1 + 4 * q);
                    h[2 * q]     = fma2(bs1, b.x, h[2 * q]);
                    h[2 * q + 1] = fma2(bs1, b.y, h[2 * q + 1]);
                }
            }
            #pragma unroll
            for (int q = 0; q < 16; ++q) {
                float a, b; unpk(h[q], a, b);
                s1 += a + b;
                s2 = fmaf(a, a, s2); s2 = fmaf(b, b, s2);
            }
        }
        {
            float mu  = s1 * (1.0f / ED);
            float var = s2 * (1.0f / ED) - mu * mu;
            float rstd = rsqrtf(var + 1e-5f);
            // half 0 from Hs
            #pragma unroll
            for (int q = 0; q < 16; ++q) {
                float a, b; unpk(*(ull*)&bufw[lane * 34 + 2 * q], a, b);
                float2 g2 = __ldg((const float2*)(ln_g + i * ED) + q);
                float2 e2 = __ldg((const float2*)(ln_b + i * ED) + q);
                float r0 = fmaf((a - mu) * rstd, g2.x, e2.x);
                float r1 = fmaf((b - mu) * rstd, g2.y, e2.y);
                bb[q] = add2(bb[q], pk2(r0, r1));
            }
            // half 1 from regs
            #pragma unroll
            for (int q = 0; q < 16; ++q) {
                float a, b; unpk(h[q], a, b);
                float2 g2 = __ldg((const float2*)(ln_g + i * ED + 32) + q);
                float2 e2 = __ldg((const float2*)(ln_b + i * ED + 32) + q);
                float r0 = fmaf((a - mu) * rstd, g2.x, e2.x);
                float r1 = fmaf((b - mu) * rstd, g2.y, e2.y);
                bb[16 + q] = add2(bb[16 + q], pk2(r0, r1));
            }
        }
    }

    // ===== epilogue: z-mean over 8-lane groups, write out[e][y][x] =====
    {
        int cell = p >> 3;
        int iy = cell & 127;
        int ix = cell >> 7;
        int cidx = iy * XD + ix;
        bool writer = (lane & 7) == 0;
        #pragma unroll
        for (int q = 0; q < 32; ++q) {
            float a, b; unpk(bb[q], a, b);
            #pragma unroll
            for (int o = 1; o < 8; o <<= 1) {
                a += __shfl_xor_sync(0xffffffffu, a, o);
                b += __shfl_xor_sync(0xffffffffu, b, o);
            }
            if (writer) {
                out[(2 * q)     * (XD * YD) + cidx] = a * 0.125f;
                out[(2 * q + 1) * (XD * YD) + cidx] = b * 0.125f;
            }
        }
    }
}

// ---------------------------------------------------------------------------
extern "C" void kernel_launch(void* const* d_in, const int* in_sizes, int n_in,
                              void* d_out, int out_size) {
    const float* Tv     = (const float*)d_in[0];
    const float* intr   = (const float*)d_in[1];
    const float* img    = (const float*)d_in[2];
    const float* bev_in = (const float*)d_in[3];
    const float* W_off  = (const float*)d_in[4];
    const float* b_off  = (const float*)d_in[5];
    const float* s_off  = (const float*)d_in[6];
    const float* W_w    = (const float*)d_in[7];
    const float* b_w    = (const float*)d_in[8];
    const float* W_l    = (const float*)d_in[9];
    const float* b_l    = (const float*)d_in[10];
    const float* ln_g   = (const float*)d_in[11];
    const float* ln_b   = (const float*)d_in[12];
    float* out = (float*)d_out;

    const int SMEM = 20736 * 4;
    static int attr_set = 0;
    cudaFuncSetAttribute(bev_kernel, cudaFuncAttributeMaxDynamicSharedMemorySize, SMEM);
    (void)attr_set;

    transpose_img_kernel<<<HW / 32, 256>>>(img);
    pack_wd_kernel<<<(NITER * ED * 12 + 255) / 256, 256>>>(W_off, W_w);
    bev_kernel<<<NPTS / 256, 256, SMEM>>>(Tv, intr, bev_in,
                                          b_off, s_off, b_w,
                                          W_l, b_l, ln_g, ln_b, out);
}

// round 4
// speedup vs baseline: 2.7565x; 1.0340x over previous
#include <cuda_runtime.h>
#include <cuda_fp16.h>

#define XD 128
#define YD 128
#define ZD 8
#define ED 64
#define NITER 3
#define FHD 96
#define FWD 320
#define NPTS (XD*YD*ZD)
#define HW (FHD*FWD)

typedef unsigned long long ull;

__device__ __half g_imgTh[HW * ED];     // (H,W,C) image in fp16, 3.9 MB
__device__ float  g_Wd[NITER * ED * 12]; // packed [iter][e][12]: Woff(6)|Ww(3)|pad

__device__ __forceinline__ ull pk2(float x, float y) {
    ull r; asm("mov.b64 %0,{%1,%2};" : "=l"(r) : "f"(x), "f"(y)); return r;
}
__device__ __forceinline__ ull splat(float x) { return pk2(x, x); }
__device__ __forceinline__ void unpk(ull v, float& x, float& y) {
    asm("mov.b64 {%0,%1},%2;" : "=f"(x), "=f"(y) : "l"(v));
}
__device__ __forceinline__ ull fma2(ull a, ull b, ull c) {
    ull d; asm("fma.rn.f32x2 %0,%1,%2,%3;" : "=l"(d) : "l"(a), "l"(b), "l"(c)); return d;
}
__device__ __forceinline__ ull add2(ull a, ull b) {
    ull d; asm("add.rn.f32x2 %0,%1,%2;" : "=l"(d) : "l"(a), "l"(b)); return d;
}

// ---------------------------------------------------------------------------
// Kernel 1: coalesced transpose img (C,H,W) -> (H,W,C) fp16
// ---------------------------------------------------------------------------
__global__ __launch_bounds__(256) void transpose_img_kernel(const float* __restrict__ img) {
    __shared__ float tile[32][65];
    const int r0 = blockIdx.x * 32;
    const int t  = threadIdx.x;
    const int tx = t & 31, ty = t >> 5;
    #pragma unroll
    for (int k = 0; k < 8; ++k) {
        int c = k * 8 + ty;
        tile[tx][c] = img[c * HW + r0 + tx];
    }
    __syncthreads();
    #pragma unroll
    for (int k = 0; k < 8; ++k) {
        int row = k * 4 + (t >> 6);
        int c   = t & 63;
        g_imgTh[(r0 + row) * ED + c] = __float2half(tile[row][c]);
    }
}

// ---------------------------------------------------------------------------
// Kernel 1b: pack W_off | W_w into g_Wd [iter][64][12]
// ---------------------------------------------------------------------------
__global__ void pack_wd_kernel(const float* __restrict__ W_off, const float* __restrict__ W_w) {
    int idx = blockIdx.x * blockDim.x + threadIdx.x;
    if (idx >= NITER * ED * 12) return;
    int i = idx / (ED * 12);
    int r = idx - i * (ED * 12);
    int e = r / 12, j = r - e * 12;
    float v = 0.0f;
    if (j < 6)      v = W_off[i * ED * 6 + e * 6 + j];
    else if (j < 9) v = W_w[i * ED * 3 + e * 3 + (j - 6)];
    g_Wd[idx] = v;
}

// ---------------------------------------------------------------------------
// Kernel 2: fused pipeline. 256 threads = 8 warps; each LANE owns one point.
// smem (floats): Wl[4096] | Wd[768] | Gs[8][32*28]=7168 | buf[8][1088]=8704
// ---------------------------------------------------------------------------
__global__ __launch_bounds__(256, 2) void bev_kernel(
    const float* __restrict__ Tv,     const float* __restrict__ intr,
    const float* __restrict__ bev_in,
    const float* __restrict__ b_off,  const float* __restrict__ s_off,
    const float* __restrict__ b_w,
    const float* __restrict__ W_l,    const float* __restrict__ b_l,
    const float* __restrict__ ln_g,   const float* __restrict__ ln_b,
    float* __restrict__ out)
{
    extern __shared__ float sm[];
    float* sWl = sm;                       // [64][64]
    float* sWd = sm + 4096;                // [64][12]
    const int t    = threadIdx.x;
    const int warp = t >> 5;
    const int lane = t & 31;
    float* Gsw  = sm + 4096 + 768 + warp * (32 * 28);   // [32][28]
    float* bufw = sm + 4096 + 768 + 7168 + warp * 1088; // Fs[16][66] / Hs[32][34]

    const int p = blockIdx.x * 256 + t;

    // ---- projected base coords ----
    float pxb, pyb;
    {
        int iz = p & 7;
        int ixy = p >> 3;
        int iy = ixy & 127;
        int ix = ixy >> 7;
        float gx = (float)ix * 0.8f;
        float gy = 51.2f - (float)iy * 0.8f;
        float gz = (float)iz * 0.5f - 2.5f;
        float q0 = Tv[0]*gx + Tv[1]*gy + Tv[2]*gz  + Tv[3];
        float q1 = Tv[4]*gx + Tv[5]*gy + Tv[6]*gz  + Tv[7];
        float q2 = Tv[8]*gx + Tv[9]*gy + Tv[10]*gz + Tv[11];
        float r0 = intr[0]*q0 + intr[1]*q1 + intr[2]*q2;
        float r1 = intr[3]*q0 + intr[4]*q1 + intr[5]*q2;
        float r2 = intr[6]*q0 + intr[7]*q1 + intr[8]*q2;
        float invz = 1.0f / r2;
        float cx = r0 * invz * (1.0f / 640.0f) - 1.0f;
        float cy = r1 * invz * (1.0f / 192.0f) - 1.0f;
        pxb = cx * 160.0f + 159.5f;
        pyb = cy * 48.0f  + 47.5f;
    }

    // ---- load B state into registers via smem transpose ----
    ull bb[32];
    const int pwarp0 = blockIdx.x * 256 + warp * 32;
    #pragma unroll
    for (int g = 0; g < 2; ++g) {
        #pragma unroll
        for (int q = 0; q < 16; ++q) {
            int pt = pwarp0 + g * 16 + q;
            ull v = *((const ull*)(bev_in + (size_t)pt * ED) + lane);
            *(ull*)&bufw[q * 66 + 2 * lane] = v;
        }
        __syncwarp();
        if ((lane >> 4) == g) {
            #pragma unroll
            for (int q = 0; q < 32; ++q)
                bb[q] = *(ull*)&bufw[(lane & 15) * 66 + 2 * q];
        }
        __syncwarp();
    }

    for (int i = 0; i < NITER; ++i) {
        __syncthreads();
        {
            const float4* src = (const float4*)(W_l + i * 4096);
            #pragma unroll
            for (int u = 0; u < 4; ++u)
                ((float4*)sWl)[t + u * 256] = src[t + u * 256];
            if (t < 192)
                ((float4*)sWd)[t] = ((const float4*)(g_Wd + i * 768))[t];
        }
        __syncthreads();

        // ===== dots: own point, 10 logits, broadcast weight rows =====
        float d[10];
        {
            ull acc[5] = {0, 0, 0, 0, 0};
            #pragma unroll
            for (int ep = 0; ep < 32; ++ep) {
                float be0, be1; unpk(bb[ep], be0, be1);
                ull bs0 = splat(be0), bs1 = splat(be1);
                const ulonglong2* w0 = (const ulonglong2*)&sWd[(2 * ep) * 12];
                const ulonglong2* w1 = (const ulonglong2*)&sWd[(2 * ep + 1) * 12];
                ulonglong2 wa = w0[0], wb = w0[1], wc = w0[2];
                acc[0] = fma2(bs0, wa.x, acc[0]); acc[1] = fma2(bs0, wa.y, acc[1]);
                acc[2] = fma2(bs0, wb.x, acc[2]); acc[3] = fma2(bs0, wb.y, acc[3]);
                acc[4] = fma2(bs0, wc.x, acc[4]);
                wa = w1[0]; wb = w1[1]; wc = w1[2];
                acc[0] = fma2(bs1, wa.x, acc[0]); acc[1] = fma2(bs1, wa.y, acc[1]);
                acc[2] = fma2(bs1, wb.x, acc[2]); acc[3] = fma2(bs1, wb.y, acc[3]);
                acc[4] = fma2(bs1, wc.x, acc[4]);
            }
            #pragma unroll
            for (int q = 0; q < 5; ++q) unpk(acc[q], d[2 * q], d[2 * q + 1]);
        }

        // ===== G1: per-lane offsets/softmax -> per-point gather table =====
        {
            const float sc = __ldg(s_off + i);
            float off[6];
            #pragma unroll
            for (int j = 0; j < 6; ++j) off[j] = (d[j] + __ldg(b_off + i * 6 + j)) * sc;
            float l0 = d[6] + __ldg(b_w + i * 3 + 0);
            float l1 = d[7] + __ldg(b_w + i * 3 + 1);
            float l2 = d[8] + __ldg(b_w + i * 3 + 2);
            float mx = fmaxf(l0, fmaxf(l1, l2));
            float e0 = __expf(l0 - mx), e1 = __expf(l1 - mx), e2 = __expf(l2 - mx);
            float inv = 1.0f / (e0 + e1 + e2);
            float wk[3] = {e0 * inv, e1 * inv, e2 * inv};
            float* grow = Gsw + lane * 28;
            #pragma unroll
            for (int k = 0; k < 3; ++k) {
                float px = fmaf(off[2 * k],     160.0f, pxb);
                float py = fmaf(off[2 * k + 1],  48.0f, pyb);
                float fx = floorf(px), fy = floorf(py);
                int x0 = (int)fx, y0 = (int)fy;
                float wx1 = px - fx, wy1 = py - fy;
                float wx0 = 1.0f - wx1, wy0 = 1.0f - wy1;
                bool vx0 = (unsigned)x0 < (unsigned)FWD, vx1 = (unsigned)(x0 + 1) < (unsigned)FWD;
                bool vy0 = (unsigned)y0 < (unsigned)FHD, vy1 = (unsigned)(y0 + 1) < (unsigned)FHD;
                int xc0 = min(max(x0, 0), FWD - 1), xc1 = min(max(x0 + 1, 0), FWD - 1);
                int yc0 = min(max(y0, 0), FHD - 1), yc1 = min(max(y0 + 1, 0), FHD - 1);
                int rA = yc0 * FWD, rB = yc1 * FWD;
                float W = wk[k];
                float w00 = (vx0 && vy0) ? W * wx0 * wy0 : 0.0f;
                float w01 = (vx1 && vy0) ? W * wx1 * wy0 : 0.0f;
                float w10 = (vx0 && vy1) ? W * wx0 * wy1 : 0.0f;
                float w11 = (vx1 && vy1) ? W * wx1 * wy1 : 0.0f;
                *(float4*)(grow + k * 8) = make_float4(
                    __int_as_float((rA + xc0) << 6), __int_as_float((rA + xc1) << 6),
                    __int_as_float((rB + xc0) << 6), __int_as_float((rB + xc1) << 6));
                *(float4*)(grow + k * 8 + 4) = make_float4(w00, w01, w10, w11);
            }
        }
        __syncwarp();

        // ===== G2: warp-per-point gather (fp16 image, channel-parallel) =====
        #pragma unroll 1
        for (int g = 0; g < 2; ++g) {
            #pragma unroll 2
            for (int q = 0; q < 16; ++q) {
                const float* grow = Gsw + (g * 16 + q) * 28;
                float a0 = 0.0f, a1 = 0.0f;
                #pragma unroll
                for (int k = 0; k < 3; ++k) {
                    float4 A  = *(const float4*)(grow + k * 8);
                    float4 Wt = *(const float4*)(grow + k * 8 + 4);
                    float2 v;
                    v = __half22float2(*(const __half2*)(g_imgTh + __float_as_int(A.x) + 2 * lane));
                    a0 = fmaf(Wt.x, v.x, a0); a1 = fmaf(Wt.x, v.y, a1);
                    v = __half22float2(*(const __half2*)(g_imgTh + __float_as_int(A.y) + 2 * lane));
                    a0 = fmaf(Wt.y, v.x, a0); a1 = fmaf(Wt.y, v.y, a1);
                    v = __half22float2(*(const __half2*)(g_imgTh + __float_as_int(A.z) + 2 * lane));
                    a0 = fmaf(Wt.z, v.x, a0); a1 = fmaf(Wt.z, v.y, a1);
                    v = __half22float2(*(const __half2*)(g_imgTh + __float_as_int(A.w) + 2 * lane));
                    a0 = fmaf(Wt.w, v.x, a0); a1 = fmaf(Wt.w, v.y, a1);
                }
                *(ull*)&bufw[q * 66 + 2 * lane] = pk2(a0, a1);
            }
            __syncwarp();
            if ((lane >> 4) == g) {
                #pragma unroll
                for (int q = 0; q < 32; ++q)
                    bb[q] = add2(bb[q], *(ull*)&bufw[(lane & 15) * 66 + 2 * q]);
            }
            __syncwarp();
        }

        // ===== matvec 64x64 (two 32-output halves) + LayerNorm residual =====
        float s1 = 0.0f, s2 = 0.0f;
        ull h[16];

        {
            #pragma unroll
            for (int q = 0; q < 8; ++q) {
                ulonglong2 bl = __ldg((const ulonglong2*)(b_l + i * ED) + q);
                h[2 * q] = bl.x; h[2 * q + 1] = bl.y;
            }
            #pragma unroll
            for (int ep = 0; ep < 32; ++ep) {
                float be0, be1; unpk(bb[ep], be0, be1);
                ull bs0 = splat(be0), bs1 = splat(be1);
                const float* w0 = &sWl[(2 * ep) * ED];
                const float* w1 = w0 + ED;
                #pragma unroll
                for (int q = 0; q < 8; ++q) {
                    ulonglong2 a = *(const ulonglong2*)(w0 + 4 * q);
                    h[2 * q]     = fma2(bs0, a.x, h[2 * q]);
                    h[2 * q + 1] = fma2(bs0, a.y, h[2 * q + 1]);
                    ulonglong2 b = *(const ulonglong2*)(w1 + 4 * q);
                    h[2 * q]     = fma2(bs1, b.x, h[2 * q]);
                    h[2 * q + 1] = fma2(bs1, b.y, h[2 * q + 1]);
                }
            }
            #pragma unroll
            for (int q = 0; q < 16; ++q) {
                float a, b; unpk(h[q], a, b);
                s1 += a + b;
                s2 = fmaf(a, a, s2); s2 = fmaf(b, b, s2);
                *(ull*)&bufw[lane * 34 + 2 * q] = h[q];
            }
        }
        {
            #pragma unroll
            for (int q = 0; q < 8; ++q) {
                ulonglong2 bl = __ldg((const ulonglong2*)(b_l + i * ED + 32) + q);
                h[2 * q] = bl.x; h[2 * q + 1] = bl.y;
            }
            #pragma unroll
            for (int ep = 0; ep < 32; ++ep) {
                float be0, be1; unpk(bb[ep], be0, be1);
                ull bs0 = splat(be0), bs1 = splat(be1);
                const float* w0 = &sWl[(2 * ep) * ED + 32];
                const float* w1 = w0 + ED;
                #pragma unroll
                for (int q = 0; q < 8; ++q) {
                    ulonglong2 a = *(const ulonglong2*)(w0 + 4 * q);
                    h[2 * q]     = fma2(bs0, a.x, h[2 * q]);
                    h[2 * q + 1] = fma2(bs0, a.y, h[2 * q + 1]);
                    ulonglong2 b = *(const ulonglong2*)(w1 + 4 * q);
                    h[2 * q]     = fma2(bs1, b.x, h[2 * q]);
                    h[2 * q + 1] = fma2(bs1, b.y, h[2 * q + 1]);
                }
            }
            #pragma unroll
            for (int q = 0; q < 16; ++q) {
                float a, b; unpk(h[q], a, b);
                s1 += a + b;
                s2 = fmaf(a, a, s2); s2 = fmaf(b, b, s2);
            }
        }
        {
            float mu  = s1 * (1.0f / ED);
            float var = s2 * (1.0f / ED) - mu * mu;
            float rstd = rsqrtf(var + 1e-5f);
            #pragma unroll
            for (int q = 0; q < 16; ++q) {
                float a, b; unpk(*(ull*)&bufw[lane * 34 + 2 * q], a, b);
                float2 g2 = __ldg((const float2*)(ln_g + i * ED) + q);
                float2 e2 = __ldg((const float2*)(ln_b + i * ED) + q);
                float r0 = fmaf((a - mu) * rstd, g2.x, e2.x);
                float r1 = fmaf((b - mu) * rstd, g2.y, e2.y);
                bb[q] = add2(bb[q], pk2(r0, r1));
            }
            #pragma unroll
            for (int q = 0; q < 16; ++q) {
                float a, b; unpk(h[q], a, b);
                float2 g2 = __ldg((const float2*)(ln_g + i * ED + 32) + q);
                float2 e2 = __ldg((const float2*)(ln_b + i * ED + 32) + q);
                float r0 = fmaf((a - mu) * rstd, g2.x, e2.x);
                float r1 = fmaf((b - mu) * rstd, g2.y, e2.y);
                bb[16 + q] = add2(bb[16 + q], pk2(r0, r1));
            }
        }
    }

    // ===== epilogue: z-mean over 8-lane groups =====
    {
        int cell = p >> 3;
        int iy = cell & 127;
        int ix = cell >> 7;
        int cidx = iy * XD + ix;
        bool writer = (lane & 7) == 0;
        #pragma unroll
        for (int q = 0; q < 32; ++q) {
            float a, b; unpk(bb[q], a, b);
            #pragma unroll
            for (int o = 1; o < 8; o <<= 1) {
                a += __shfl_xor_sync(0xffffffffu, a, o);
                b += __shfl_xor_sync(0xffffffffu, b, o);
            }
            if (writer) {
                out[(2 * q)     * (XD * YD) + cidx] = a * 0.125f;
                out[(2 * q + 1) * (XD * YD) + cidx] = b * 0.125f;
            }
        }
    }
}

// ---------------------------------------------------------------------------
extern "C" void kernel_launch(void* const* d_in, const int* in_sizes, int n_in,
                              void* d_out, int out_size) {
    const float* Tv     = (const float*)d_in[0];
    const float* intr   = (const float*)d_in[1];
    const float* img    = (const float*)d_in[2];
    const float* bev_in = (const float*)d_in[3];
    const float* W_off  = (const float*)d_in[4];
    const float* b_off  = (const float*)d_in[5];
    const float* s_off  = (const float*)d_in[6];
    const float* W_w    = (const float*)d_in[7];
    const float* b_w    = (const float*)d_in[8];
    const float* W_l    = (const float*)d_in[9];
    const float* b_l    = (const float*)d_in[10];
    const float* ln_g   = (const float*)d_in[11];
    const float* ln_b   = (const float*)d_in[12];
    float* out = (float*)d_out;

    const int SMEM = 20736 * 4;
    cudaFuncSetAttribute(bev_kernel, cudaFuncAttributeMaxDynamicSharedMemorySize, SMEM);

    transpose_img_kernel<<<HW / 32, 256>>>(img);
    pack_wd_kernel<<<(NITER * ED * 12 + 255) / 256, 256>>>(W_off, W_w);
    bev_kernel<<<NPTS / 256, 256, SMEM>>>(Tv, intr, bev_in,
                                          b_off, s_off, b_w,
                                          W_l, b_l, ln_g, ln_b, out);
}